// round 5
// baseline (speedup 1.0000x reference)
#include <cuda_runtime.h>

// AdditiveAttention: B=2, L=512, S=512, H=8, E=32, D=64 (fp32)
// scores[b,h,l,s] = sum_e tanh(q[b,l,h,e]+k[b,s,h,e])*v[e] + mask[l,s] + klen[b,s]
// A = softmax_s(scores); out[b,l,h,d] = sum_s A * values[b,s,h,d]

#define Bb 2
#define Lq 512
#define Sk 512
#define Hh 8
#define Ee 32
#define Dd 64
#define BLK_L 64
#define SS_STRIDE 513   // padded row stride for scores (conflict-free across l)

// smem floats: K tile + scores + max red + sum red + inv
#define SMEM_FLOATS (Sk*Ee + BLK_L*SS_STRIDE + BLK_L*4 + BLK_L*4 + BLK_L)
#define SMEM_BYTES (SMEM_FLOATS * 4)

__device__ __forceinline__ float fast_tanh(float x) {
    float y;
    asm("tanh.approx.f32 %0, %1;" : "=f"(y) : "f"(x));
    return y;
}

extern __shared__ float smem[];

__global__ __launch_bounds__(256, 1)
void addattn_kernel(const float* __restrict__ q_g,
                    const float* __restrict__ k_g,
                    const float* __restrict__ val_g,
                    const float* __restrict__ vvec,
                    const float* __restrict__ mask,
                    const float* __restrict__ klen,
                    float* __restrict__ out)
{
    float* sK   = smem;                       // [Sk][Ee]
    float* sS   = sK + Sk * Ee;               // [BLK_L][SS_STRIDE]
    float* redm = sS + BLK_L * SS_STRIDE;     // [BLK_L][4]
    float* reds = redm + BLK_L * 4;           // [BLK_L][4]
    float* sInv = reds + BLK_L * 4;           // [BLK_L]

    const int t  = threadIdx.x;
    const int lb = blockIdx.x;   // 0..7  (L block)
    const int h  = blockIdx.y;   // 0..7
    const int b  = blockIdx.z;   // 0..1
    const int l0 = lb * BLK_L;

    // ---- Stage K tile for (b,h): keys[((b*S+s)*H+h)*E + e] -> sK[s*E+e]
    for (int i = t; i < Sk * (Ee / 4); i += 256) {
        int s  = i / (Ee / 4);
        int e4 = i % (Ee / 4);
        const float4* src =
            (const float4*)(k_g + ((size_t)((b * Sk + s) * Hh + h)) * Ee) + e4;
        ((float4*)sK)[s * (Ee / 4) + e4] = *src;
    }

    const int l  = t & 63;       // local l row
    const int sg = t >> 6;       // 0..3 (s-stride group / d-group)
    const int lg = l0 + l;

    // q row + v into registers
    float qr[Ee], vr[Ee];
    {
        const float* qp = q_g + ((size_t)((b * Lq + lg) * Hh + h)) * Ee;
        #pragma unroll
        for (int e = 0; e < Ee; e++) {
            qr[e] = qp[e];
            vr[e] = vvec[e];
        }
    }
    __syncthreads();

    // ---- Phase 1: scores + per-thread row max
    float m = -3.4e38f;
    for (int s = sg; s < Sk; s += 4) {
        const float* kp = sK + s * Ee;
        float a0 = 0.f, a1 = 0.f, a2 = 0.f, a3 = 0.f;
        #pragma unroll
        for (int e = 0; e < Ee; e += 4) {
            a0 += vr[e + 0] * fast_tanh(qr[e + 0] + kp[e + 0]);
            a1 += vr[e + 1] * fast_tanh(qr[e + 1] + kp[e + 1]);
            a2 += vr[e + 2] * fast_tanh(qr[e + 2] + kp[e + 2]);
            a3 += vr[e + 3] * fast_tanh(qr[e + 3] + kp[e + 3]);
        }
        float sc = (a0 + a1) + (a2 + a3)
                 + mask[(size_t)lg * Sk + s] + klen[(size_t)b * Sk + s];
        sS[l * SS_STRIDE + s] = sc;
        m = fmaxf(m, sc);
    }
    redm[l * 4 + sg] = m;
    __syncthreads();

    // ---- Phase 2: softmax (exp + sum), normalized lazily via sInv
    float rm = fmaxf(fmaxf(redm[l * 4 + 0], redm[l * 4 + 1]),
                     fmaxf(redm[l * 4 + 2], redm[l * 4 + 3]));
    float sum = 0.f;
    for (int s = sg; s < Sk; s += 4) {
        float e_ = __expf(sS[l * SS_STRIDE + s] - rm);
        sS[l * SS_STRIDE + s] = e_;
        sum += e_;
    }
    reds[l * 4 + sg] = sum;
    __syncthreads();
    if (sg == 0) {
        float tot = reds[l * 4 + 0] + reds[l * 4 + 1]
                  + reds[l * 4 + 2] + reds[l * 4 + 3];
        sInv[l] = 1.0f / tot;
    }
    __syncthreads();

    // ---- Phase 3: A @ V. Thread: row l, 16 d's (dbase..dbase+15).
    const int dbase = sg * 16;
    float acc[16];
    #pragma unroll
    for (int j = 0; j < 16; j++) acc[j] = 0.f;

    // values[((b*S+s)*H+h)*D + d]
    const float* vb = val_g + ((size_t)(b * Sk * Hh + h)) * Dd + dbase;
    #pragma unroll 2
    for (int s = 0; s < Sk; s++) {
        float a = sS[l * SS_STRIDE + s];
        const float4* vp = (const float4*)(vb + (size_t)s * Hh * Dd);
        float4 w0 = vp[0], w1 = vp[1], w2 = vp[2], w3 = vp[3];
        acc[0]  += a * w0.x; acc[1]  += a * w0.y; acc[2]  += a * w0.z; acc[3]  += a * w0.w;
        acc[4]  += a * w1.x; acc[5]  += a * w1.y; acc[6]  += a * w1.z; acc[7]  += a * w1.w;
        acc[8]  += a * w2.x; acc[9]  += a * w2.y; acc[10] += a * w2.z; acc[11] += a * w2.w;
        acc[12] += a * w3.x; acc[13] += a * w3.y; acc[14] += a * w3.z; acc[15] += a * w3.w;
    }
    float inv = sInv[l];
    float* op = out + ((size_t)((b * Lq + lg) * Hh + h)) * Dd + dbase;
    #pragma unroll
    for (int j = 0; j < 16; j++) op[j] = acc[j] * inv;
}

extern "C" void kernel_launch(void* const* d_in, const int* in_sizes, int n_in,
                              void* d_out, int out_size)
{
    const float* q    = (const float*)d_in[0];
    const float* k    = (const float*)d_in[1];
    const float* vals = (const float*)d_in[2];
    const float* vvec = (const float*)d_in[3];
    const float* mask = (const float*)d_in[4];
    const float* klen = (const float*)d_in[5];

    cudaFuncSetAttribute(addattn_kernel,
                         cudaFuncAttributeMaxDynamicSharedMemorySize, SMEM_BYTES);

    dim3 grid(Lq / BLK_L, Hh, Bb);
    addattn_kernel<<<grid, 256, SMEM_BYTES>>>(q, k, vals, vvec, mask, klen,
                                              (float*)d_out);
}

// round 8
// speedup vs baseline: 1.1504x; 1.1504x over previous
#include <cuda_runtime.h>

// AdditiveAttention: B=2, L=512, S=512, H=8, E=32, D=64 (fp32)
// scores[b,h,l,s] = sum_e tanh(q[b,l,h,e]+k[b,s,h,e])*v[e] + mask[l,s] + klen[b,s]
// A = softmax_s(scores); out[b,l,h,d] = sum_s A * values[b,s,h,d]

#define Bb 2
#define Lq 512
#define Sk 512
#define Hh 8
#define Ee 32
#define Dd 64
#define BLK_L 64
#define NT 512
#define SS_STRIDE 513   // padded row stride for scores (conflict-free)

// smem floats: K tile + scores + max red + sum red + inv
#define SMEM_FLOATS (Sk*Ee + BLK_L*SS_STRIDE + BLK_L*8 + BLK_L*8 + BLK_L)
#define SMEM_BYTES (SMEM_FLOATS * 4)

__device__ __forceinline__ float fast_tanh(float x) {
    float y;
    asm("tanh.approx.f32 %0, %1;" : "=f"(y) : "f"(x));
    return y;
}

__device__ __forceinline__ unsigned long long pack2(float lo, float hi) {
    unsigned long long r;
    asm("mov.b64 %0, {%1, %2};" : "=l"(r) : "f"(lo), "f"(hi));
    return r;
}

#define FFMA2(d, a, b, c) \
    asm("fma.rn.f32x2 %0, %1, %2, %3;" : "=l"(d) : "l"(a), "l"(b), "l"(c))

extern __shared__ float smem[];

__global__ __launch_bounds__(NT, 1)
void addattn_kernel(const float* __restrict__ q_g,
                    const float* __restrict__ k_g,
                    const float* __restrict__ val_g,
                    const float* __restrict__ vvec,
                    const float* __restrict__ mask,
                    const float* __restrict__ klen,
                    float* __restrict__ out)
{
    float* sK   = smem;                       // [Sk][Ee]
    float* sS   = sK + Sk * Ee;               // [BLK_L][SS_STRIDE]
    float* redm = sS + BLK_L * SS_STRIDE;     // [BLK_L][8]
    float* reds = redm + BLK_L * 8;           // [BLK_L][8]
    float* sInv = reds + BLK_L * 8;           // [BLK_L]

    const int t  = threadIdx.x;
    const int lb = blockIdx.x;   // 0..7  (L block)
    const int h  = blockIdx.y;   // 0..7
    const int b  = blockIdx.z;   // 0..1
    const int l0 = lb * BLK_L;

    // ---- Stage K tile for (b,h): keys[((b*S+s)*H+h)*E + e] -> sK[s*E+e]
    for (int i = t; i < Sk * (Ee / 4); i += NT) {
        int s  = i >> 3;          // Ee/4 = 8
        int e4 = i & 7;
        const float4* src =
            (const float4*)(k_g + ((size_t)((b * Sk + s) * Hh + h)) * Ee) + e4;
        ((float4*)sK)[s * (Ee / 4) + e4] = *src;
    }

    const int l  = t & 63;       // local l row
    const int sg = t >> 6;       // 0..7
    const int lg = l0 + l;

    // q row + v into registers
    float qr[Ee], vr[Ee];
    {
        const float* qp = q_g + ((size_t)((b * Lq + lg) * Hh + h)) * Ee;
        #pragma unroll
        for (int e = 0; e < Ee; e++) {
            qr[e] = qp[e];
            vr[e] = vvec[e];
        }
    }
    __syncthreads();

    // ---- Phase 1: raw scores (no mask). k-loads are warp-broadcast LDS.
    for (int s = sg; s < Sk; s += 8) {
        const float* kp = sK + s * Ee;
        float a0 = 0.f, a1 = 0.f, a2 = 0.f, a3 = 0.f;
        #pragma unroll
        for (int e = 0; e < Ee; e += 4) {
            a0 += vr[e + 0] * fast_tanh(qr[e + 0] + kp[e + 0]);
            a1 += vr[e + 1] * fast_tanh(qr[e + 1] + kp[e + 1]);
            a2 += vr[e + 2] * fast_tanh(qr[e + 2] + kp[e + 2]);
            a3 += vr[e + 3] * fast_tanh(qr[e + 3] + kp[e + 3]);
        }
        sS[l * SS_STRIDE + s] = (a0 + a1) + (a2 + a3);
    }
    __syncthreads();

    // ---- Phase 1b: coalesced mask + klen add (thread = column s)
    {
        const int s = t;                       // 0..511
        const float kl = klen[(size_t)b * Sk + s];
        const float* mp = mask + (size_t)l0 * Sk + s;
        float* sp = sS + s;
        #pragma unroll 4
        for (int ll = 0; ll < BLK_L; ll++) {
            sp[ll * SS_STRIDE] += mp[(size_t)ll * Sk] + kl;
        }
    }
    __syncthreads();

    // ---- Phase 2a: row max (conflict-free LDS, stride 513)
    {
        float m = -3.4e38f;
        #pragma unroll 4
        for (int s = sg; s < Sk; s += 8)
            m = fmaxf(m, sS[l * SS_STRIDE + s]);
        redm[l * 8 + sg] = m;
    }
    __syncthreads();
    float rm;
    {
        const float* r = redm + l * 8;
        rm = fmaxf(fmaxf(fmaxf(r[0], r[1]), fmaxf(r[2], r[3])),
                   fmaxf(fmaxf(r[4], r[5]), fmaxf(r[6], r[7])));
    }

    // ---- Phase 2b: exp + sum
    {
        float sum = 0.f;
        #pragma unroll 4
        for (int s = sg; s < Sk; s += 8) {
            float e_ = __expf(sS[l * SS_STRIDE + s] - rm);
            sS[l * SS_STRIDE + s] = e_;
            sum += e_;
        }
        reds[l * 8 + sg] = sum;
    }
    __syncthreads();
    if (sg == 0) {
        const float* r = reds + l * 8;
        float tot = ((r[0] + r[1]) + (r[2] + r[3]))
                  + ((r[4] + r[5]) + (r[6] + r[7]));
        sInv[l] = 1.0f / tot;
    }
    __syncthreads();

    // ---- Phase 3: A @ V with packed fma.rn.f32x2.
    // Thread: row l, 8 d's (dg*8 .. dg*8+7) -> 4 packed accumulators.
    const int dbase = sg * 8;
    unsigned long long acc0 = 0, acc1 = 0, acc2 = 0, acc3 = 0;

    // values[((b*S+s)*H+h)*D + d]; warp-broadcast LDG (same addr across lanes)
    const float* vb = val_g + ((size_t)(b * Sk * Hh + h)) * Dd + dbase;
    #pragma unroll 4
    for (int s = 0; s < Sk; s++) {
        float a = sS[l * SS_STRIDE + s];
        unsigned long long ap = pack2(a, a);
        const ulonglong2* vp = (const ulonglong2*)(vb + (size_t)s * Hh * Dd);
        ulonglong2 w01 = vp[0];
        ulonglong2 w23 = vp[1];
        FFMA2(acc0, ap, w01.x, acc0);
        FFMA2(acc1, ap, w01.y, acc1);
        FFMA2(acc2, ap, w23.x, acc2);
        FFMA2(acc3, ap, w23.y, acc3);
    }

    float inv = sInv[l];
    float2 o0 = *(float2*)&acc0, o1 = *(float2*)&acc1;
    float2 o2 = *(float2*)&acc2, o3 = *(float2*)&acc3;
    float4 r0 = make_float4(o0.x * inv, o0.y * inv, o1.x * inv, o1.y * inv);
    float4 r1 = make_float4(o2.x * inv, o2.y * inv, o3.x * inv, o3.y * inv);
    float4* op = (float4*)(out + ((size_t)((b * Lq + lg) * Hh + h)) * Dd + dbase);
    op[0] = r0;
    op[1] = r1;
}

extern "C" void kernel_launch(void* const* d_in, const int* in_sizes, int n_in,
                              void* d_out, int out_size)
{
    const float* q    = (const float*)d_in[0];
    const float* k    = (const float*)d_in[1];
    const float* vals = (const float*)d_in[2];
    const float* vvec = (const float*)d_in[3];
    const float* mask = (const float*)d_in[4];
    const float* klen = (const float*)d_in[5];

    cudaFuncSetAttribute(addattn_kernel,
                         cudaFuncAttributeMaxDynamicSharedMemorySize, SMEM_BYTES);

    dim3 grid(Lq / BLK_L, Hh, Bb);
    addattn_kernel<<<grid, NT, SMEM_BYTES>>>(q, k, vals, vvec, mask, klen,
                                             (float*)d_out);
}